// round 3
// baseline (speedup 1.0000x reference)
#include <cuda_runtime.h>
#include <math.h>

#define B_  32
#define T_  1024
#define C_  128
#define G_  896
#define G3_ 2688
#define H_  896
#define NB  112      // persistent CTAs for the scan (1/SM guaranteed by smem)

typedef unsigned long long u64;

// ---------------- device scratch (allocation-free: __device__ globals) -------
// __align__(256): these are accessed as float2/float4; plain float[] only
// guarantees 4B alignment -> vector ld/st would trap.
__device__ __align__(256) float g_gx[(size_t)T_ * G3_ * B_];   // [T][3G][B]
__device__ __align__(256) float g_hs[(size_t)T_ * G_  * B_];   // [T][G][B]
__device__ __align__(256) float g_h [2 * G_ * B_];             // double-buffered h, [G][B]
__device__ unsigned g_bar_count = 0;            // self-restoring barrier state
__device__ volatile unsigned g_bar_gen = 0;

// ---------------- packed f32x2 helpers --------------------------------------
__device__ __forceinline__ void fma2(u64 &acc, u64 a, u64 b) {
    asm("fma.rn.f32x2 %0, %1, %2, %0;" : "+l"(acc) : "l"(a), "l"(b));
}
__device__ __forceinline__ u64 pack2(float x, float y) {
    u64 r; asm("mov.b64 %0, {%1,%2};" : "=l"(r) : "f"(x), "f"(y)); return r;
}
__device__ __forceinline__ float2 unpack2(u64 v) {
    float2 r; asm("mov.b64 {%0,%1}, %2;" : "=f"(r.x), "=f"(r.y) : "l"(v)); return r;
}
__device__ __forceinline__ float sigm(float x) { return 1.0f / (1.0f + __expf(-x)); }

// ============================================================================
// h0[g][b] = state[0][b][g]
// ============================================================================
__global__ void k_init(const float* __restrict__ state) {
    int i = blockIdx.x * blockDim.x + threadIdx.x;
    if (i < G_ * B_) {
        int g = i >> 5, b = i & 31;
        g_h[g * 32 + b] = state[b * G_ + g];
    }
}

// ============================================================================
// gx[t][row][b] = b_ih[row] + sum_c x[b][t][c] * w_ih[row][c]
// grid (42 row-tiles of 64, 1024 t), 128 threads
// ============================================================================
__global__ __launch_bounds__(128) void k_gx(const float* __restrict__ x,
                                            const float* __restrict__ w_ih,
                                            const float* __restrict__ b_ih) {
    __shared__ float ws[128 * 64];   // [c][r]
    __shared__ float xs[128 * 32];   // [c][b]
    const int tid = threadIdx.x;
    const int r0  = blockIdx.x * 64;
    const int t   = blockIdx.y;

    for (int i = tid; i < 64 * 32; i += 128) {
        int r = i >> 5, cq = (i & 31) * 4;
        float4 v = *(const float4*)(w_ih + (size_t)(r0 + r) * C_ + cq);
        ws[(cq+0)*64 + r] = v.x; ws[(cq+1)*64 + r] = v.y;
        ws[(cq+2)*64 + r] = v.z; ws[(cq+3)*64 + r] = v.w;
    }
    for (int i = tid; i < 32 * 32; i += 128) {
        int b = i >> 5, cq = (i & 31) * 4;
        float4 v = *(const float4*)(x + ((size_t)b * T_ + t) * C_ + cq);
        xs[(cq+0)*32 + b] = v.x; xs[(cq+1)*32 + b] = v.y;
        xs[(cq+2)*32 + b] = v.z; xs[(cq+3)*32 + b] = v.w;
    }
    __syncthreads();

    const int rt  = tid >> 3;       // 0..15 -> 4 rows each
    const int bpt = tid & 7;        // 0..7  -> 4 b each (2 float2 pairs)
    const int rr  = rt * 4;
    const int bb  = bpt * 4;
    u64 acc[4][2] = {};

#pragma unroll 2
    for (int k = 0; k < 128; ++k) {
        const float* wk = ws + k * 64 + rr;
        u64 h0 = *(const u64*)(xs + k * 32 + bb);
        u64 h1 = *(const u64*)(xs + k * 32 + bb + 2);
#pragma unroll
        for (int i = 0; i < 4; ++i) {
            u64 wp = pack2(wk[i], wk[i]);
            fma2(acc[i][0], wp, h0);
            fma2(acc[i][1], wp, h1);
        }
    }
#pragma unroll
    for (int i = 0; i < 4; ++i) {
        float bias = b_ih[r0 + rr + i];
        float* op = g_gx + ((size_t)t * G3_ + r0 + rr + i) * B_ + bb;
        float2 a0 = unpack2(acc[i][0]); a0.x += bias; a0.y += bias;
        float2 a1 = unpack2(acc[i][1]); a1.x += bias; a1.y += bias;
        *(float2*)(op)     = a0;
        *(float2*)(op + 2) = a1;
    }
}

// ============================================================================
// Persistent GRU scan. 112 CTAs x 256 threads. CTA owns j in [cta*8, cta*8+8).
// SMEM: hs[896][32] (114688B) + ws[896][24] (86016B) + red (9216B) = 209920B
// 209920B > 114KB -> at most 1 CTA/SM; grid 112 <= SM count -> all co-resident
// in wave 1, so the grid barrier cannot deadlock.
// ============================================================================
#define RNN_SMEM ((G_*B_ + 896*24 + 3*64*12) * 4)

__global__ __launch_bounds__(256) void k_rnn(const float* __restrict__ w_hh,
                                             const float* __restrict__ b_hh) {
    extern __shared__ float sm[];
    float* hs  = sm;                  // [896][32]  current h
    float* ws  = sm + G_ * B_;        // [896][24]  k-major w_hh slice
    float* red = ws + 896 * 24;       // [3][64][12] k-split reduction

    const int tid = threadIdx.x;
    const int cta = blockIdx.x;
    const int j0  = cta * 8;

    // load this CTA's 24 w_hh rows, transposed to k-major (one-time cost)
    for (int lr = 0; lr < 24; ++lr) {
        int gate = lr >> 3, jl = lr & 7;
        const float* src = w_hh + (size_t)(gate * G_ + j0 + jl) * G_;
        for (int k = tid; k < G_; k += 256) ws[k * 24 + lr] = src[k];
    }

    const int ksplit = tid >> 6;      // 0..3, 224 k each
    const int tile   = tid & 63;
    const int jl     = tile >> 3;     // 0..7
    const int bpt    = tile & 7;      // 0..7
    const int bb     = bpt * 4;
    const int jg     = j0 + jl;

    float bhr = 0.f, bhz = 0.f, bhn = 0.f;
    if (tid < 64) {
        bhr = b_hh[jg];
        bhz = b_hh[G_ + jg];
        bhn = b_hh[2 * G_ + jg];
    }

    for (int t = 0; t < T_; ++t) {
        const int cur = t & 1, nxt = cur ^ 1;
        const float* hg = g_h + cur * (G_ * B_);

        // pull current h into SMEM (L2-only loads: other SMs wrote it)
        for (int i = tid * 4; i < G_ * B_; i += 1024) {
            float4 v = __ldcg((const float4*)(hg + i));
            *(float4*)(hs + i) = v;
        }
        __syncthreads();   // also covers the one-time ws load at t==0

        u64 a[3][2] = {};
        const int k0 = ksplit * 224;
#pragma unroll 4
        for (int k = k0; k < k0 + 224; ++k) {
            const float* wk = ws + k * 24 + jl;
            u64 h0 = *(const u64*)(hs + k * 32 + bb);
            u64 h1 = *(const u64*)(hs + k * 32 + bb + 2);
            u64 wr = pack2(wk[0],  wk[0]);
            u64 wz = pack2(wk[8],  wk[8]);
            u64 wn = pack2(wk[16], wk[16]);
            fma2(a[0][0], wr, h0); fma2(a[0][1], wr, h1);
            fma2(a[1][0], wz, h0); fma2(a[1][1], wz, h1);
            fma2(a[2][0], wn, h0); fma2(a[2][1], wn, h1);
        }

        // k-split reduction via smem
        if (ksplit) {
            float2* rp = (float2*)red + ((ksplit - 1) * 64 + tile) * 6;
#pragma unroll
            for (int g = 0; g < 3; ++g) {
                rp[g * 2]     = unpack2(a[g][0]);
                rp[g * 2 + 1] = unpack2(a[g][1]);
            }
        }
        __syncthreads();

        if (tid < 64) {
            float2 av[3][2];
#pragma unroll
            for (int g = 0; g < 3; ++g) {
                av[g][0] = unpack2(a[g][0]);
                av[g][1] = unpack2(a[g][1]);
            }
#pragma unroll
            for (int s = 0; s < 3; ++s) {
                float2* rp = (float2*)red + (s * 64 + tile) * 6;
#pragma unroll
                for (int g = 0; g < 3; ++g) {
                    float2 v0 = rp[g * 2], v1 = rp[g * 2 + 1];
                    av[g][0].x += v0.x; av[g][0].y += v0.y;
                    av[g][1].x += v1.x; av[g][1].y += v1.y;
                }
            }
            const float* gxp = g_gx + (size_t)t * G3_ * B_;
            float* hn = g_h  + nxt * (G_ * B_);
            float* ho = g_hs + (size_t)t * G_ * B_;
#pragma unroll
            for (int p = 0; p < 2; ++p) {
                int bo = bb + 2 * p;
                float2 gxr  = *(const float2*)(gxp + (size_t)(jg) * B_ + bo);
                float2 gxz  = *(const float2*)(gxp + (size_t)(G_ + jg) * B_ + bo);
                float2 gxn  = *(const float2*)(gxp + (size_t)(2 * G_ + jg) * B_ + bo);
                float2 hold = *(const float2*)(hs + jg * 32 + bo);

                float rx = sigm(gxr.x + av[0][p].x + bhr);
                float ry = sigm(gxr.y + av[0][p].y + bhr);
                float zx = sigm(gxz.x + av[1][p].x + bhz);
                float zy = sigm(gxz.y + av[1][p].y + bhz);
                float nx = tanhf(gxn.x + rx * (av[2][p].x + bhn));
                float ny = tanhf(gxn.y + ry * (av[2][p].y + bhn));
                float hx = (1.f - zx) * nx + zx * hold.x;
                float hy = (1.f - zy) * ny + zy * hold.y;

                float2 hv = make_float2(hx, hy);
                *(float2*)(hn + jg * 32 + bo) = hv;
                *(float2*)(ho + jg * 32 + bo) = hv;
            }
            // GPU-scope fence by the WRITERS: their h stores must be L2-visible
            // before this CTA's barrier arrival is (threadfence orders only the
            // calling thread's writes -> every writer must fence).
            __threadfence();
        }

        // sense-reversing grid barrier (self-restoring -> replay-safe)
        __syncthreads();
        if (tid == 0) {
            unsigned old = g_bar_gen;
            if (atomicAdd(&g_bar_count, 1u) == NB - 1) {
                g_bar_count = 0;
                __threadfence();
                g_bar_gen = old + 1;
            } else {
                while (g_bar_gen == old) { __nanosleep(32); }
            }
            __threadfence();
        }
        __syncthreads();
    }
}

// ============================================================================
// out[b][t][h] = relu(sum_g hs[t][g][b] * w_post[h][g] + b_post[h])
// grid (14 h-tiles of 64, 1024 t), 128 threads
// ============================================================================
__global__ __launch_bounds__(128) void k_post(const float* __restrict__ w_post,
                                              const float* __restrict__ b_post,
                                              float* __restrict__ out) {
    __shared__ float wsc[128 * 64];  // [g_chunk][h]
    __shared__ float hsc[128 * 32];  // [g_chunk][b]
    const int tid = threadIdx.x;
    const int h0  = blockIdx.x * 64;
    const int t   = blockIdx.y;
    const int rt  = tid >> 3, bpt = tid & 7;
    const int rr  = rt * 4,   bb  = bpt * 4;
    u64 acc[4][2] = {};

    for (int ch = 0; ch < 7; ++ch) {
        const int g0 = ch * 128;
        for (int i = tid; i < 64 * 32; i += 128) {
            int r = i >> 5, cq = (i & 31) * 4;
            float4 v = *(const float4*)(w_post + (size_t)(h0 + r) * G_ + g0 + cq);
            wsc[(cq+0)*64 + r] = v.x; wsc[(cq+1)*64 + r] = v.y;
            wsc[(cq+2)*64 + r] = v.z; wsc[(cq+3)*64 + r] = v.w;
        }
        for (int i = tid; i < 1024; i += 128) {
            float4 v = *(const float4*)(g_hs + ((size_t)t * G_ + g0) * B_ + i * 4);
            *(float4*)(hsc + i * 4) = v;
        }
        __syncthreads();
#pragma unroll 2
        for (int k = 0; k < 128; ++k) {
            const float* wk = wsc + k * 64 + rr;
            u64 h0v = *(const u64*)(hsc + k * 32 + bb);
            u64 h1v = *(const u64*)(hsc + k * 32 + bb + 2);
#pragma unroll
            for (int i = 0; i < 4; ++i) {
                u64 wp = pack2(wk[i], wk[i]);
                fma2(acc[i][0], wp, h0v);
                fma2(acc[i][1], wp, h1v);
            }
        }
        __syncthreads();
    }

    float bias[4], vv[4][4];
#pragma unroll
    for (int i = 0; i < 4; ++i) bias[i] = b_post[h0 + rr + i];
#pragma unroll
    for (int i = 0; i < 4; ++i) {
        float2 a0 = unpack2(acc[i][0]), a1 = unpack2(acc[i][1]);
        vv[i][0] = fmaxf(a0.x + bias[i], 0.f);
        vv[i][1] = fmaxf(a0.y + bias[i], 0.f);
        vv[i][2] = fmaxf(a1.x + bias[i], 0.f);
        vv[i][3] = fmaxf(a1.y + bias[i], 0.f);
    }
#pragma unroll
    for (int bl = 0; bl < 4; ++bl) {
        int b = bb + bl;
        float4 o = make_float4(vv[0][bl], vv[1][bl], vv[2][bl], vv[3][bl]);
        *(float4*)(out + ((size_t)b * T_ + t) * H_ + h0 + rr) = o;
    }
}

// ============================================================================
// h_last[0][b][g] = final h (lives in g_h buffer 0 after 1024 steps)
// ============================================================================
__global__ void k_last(float* __restrict__ out) {
    int i = blockIdx.x * blockDim.x + threadIdx.x;
    if (i < G_ * B_) {
        int b = i / G_, g = i % G_;
        out[(size_t)B_ * T_ * H_ + i] = g_h[g * 32 + b];
    }
}

// ============================================================================
extern "C" void kernel_launch(void* const* d_in, const int* in_sizes, int n_in,
                              void* d_out, int out_size) {
    const float* x      = (const float*)d_in[0];
    const float* state  = (const float*)d_in[1];
    const float* w_ih   = (const float*)d_in[2];
    const float* w_hh   = (const float*)d_in[3];
    const float* b_ih   = (const float*)d_in[4];
    const float* b_hh   = (const float*)d_in[5];
    const float* w_post = (const float*)d_in[6];
    const float* b_post = (const float*)d_in[7];
    float* out = (float*)d_out;

    static int smem_set = 0;
    if (!smem_set) {
        cudaFuncSetAttribute(k_rnn, cudaFuncAttributeMaxDynamicSharedMemorySize, RNN_SMEM);
        smem_set = 1;
    }

    k_init<<<112, 256>>>(state);
    k_gx<<<dim3(42, 1024), 128>>>(x, w_ih, b_ih);
    k_rnn<<<NB, 256, RNN_SMEM>>>(w_hh, b_hh);
    k_post<<<dim3(14, 1024), 128>>>(w_post, b_post, out);
    k_last<<<112, 256>>>(out);
}